// round 14
// baseline (speedup 1.0000x reference)
#include <cuda_runtime.h>
#include <cstdint>
#include <cub/cub.cuh>

// Problem constants
#define C_DIM     4096
#define NUMEL     16777216
#define W4        (NUMEL / 4)           // 4,194,304 count words
#define NUMEL_D   16777216.0
#define MAX_K     4500000               // >= S + R = 4,404,019
#define M2        1114112               // candidate capacity: R + 64K slack
#define HIST_BINS (1u << 18)            // ordkey >> 13
#define CAPB      4096                  // smem bitonic cap per bin
#define TEMP_BYTES (32u * 1024u * 1024u)

// Static device scratch (allocation-free per harness rules)
__device__ uint32_t g_cnt[W4];                 // per-key count nibble + cursor nibble, 16MB
__device__ uint32_t g_sums[W4];                // per-word totals
__device__ uint32_t g_base[W4];                // exclusive scan of totals
__device__ unsigned long long g_z[MAX_K];      // key-grouped (origidx<<32)|valbits
__device__ uint32_t g_hord[MAX_K];             // dense head ordkeys
__device__ uint32_t g_hkey[MAX_K];             // dense head keys
__device__ uint32_t g_hist[HIST_BINS + 4];     // hist + [HIST_BINS]=hcur, [+1]=wcur
__device__ uint32_t g_binbase[HIST_BINS];      // per-bin exclusive offsets
__device__ uint32_t g_bincur[HIST_BINS];       // per-bin cursors
__device__ uint32_t g_wl[HIST_BINS];           // worklist of active bins
__device__ uint32_t g_super[1024];
__device__ uint32_t g_superbase[1024];
__device__ uint32_t g_B[1];
__device__ unsigned char g_temp[TEMP_BYTES];   // [0,16M) zbin (M2 u64), [16M,32M) cub temp

static __device__ __forceinline__ uint32_t f32_to_ord(uint32_t b) {
    return b ^ ((uint32_t)((int32_t)b >> 31) | 0x80000000u);
}
static __device__ __forceinline__ uint32_t make_key(const int* __restrict__ samp,
                                                    const int* __restrict__ ridx,
                                                    int S, int i) {
    if (i < S) return (uint32_t)samp[i];
    int r = i - S;
    return (uint32_t)ridx[2 * r] * (uint32_t)C_DIM + (uint32_t)ridx[2 * r + 1];
}

__global__ void __launch_bounds__(512) count_kernel(
        const int* __restrict__ samp, const int* __restrict__ ridx,
        int S, int K, uint32_t* __restrict__ cnt) {
    int i = blockIdx.x * 512 + threadIdx.x;
    if (i >= K) return;
    uint32_t key = make_key(samp, ridx, S, i);
    atomicAdd(&cnt[key >> 2], 1u << ((key & 3u) * 8u));
}

__global__ void __launch_bounds__(512) sums_kernel(
        const uint32_t* __restrict__ cnt, uint32_t* __restrict__ sums) {
    int w = blockIdx.x * 512 + threadIdx.x;
    if (w >= W4) return;
    uint32_t c = cnt[w];
    uint32_t p = (c & 0x00FF00FFu) + ((c >> 8) & 0x00FF00FFu);
    sums[w] = (p & 0xFFFFu) + (p >> 16);
}

__global__ void __launch_bounds__(512) scatter_kernel(
        const int* __restrict__ samp, const int* __restrict__ ridx,
        const float* __restrict__ grad, const float* __restrict__ rval,
        int S, int K, float adj,
        uint32_t* __restrict__ cnt, const uint32_t* __restrict__ base,
        unsigned long long* __restrict__ z) {
    int i = blockIdx.x * 512 + threadIdx.x;
    if (i >= K) return;
    uint32_t key = make_key(samp, ridx, S, i);
    float v = (i < S) ? fabsf(grad[i]) : adj * rval[i - S];
    uint32_t w = key >> 2, lane = key & 3u;
    uint32_t old = atomicAdd(&cnt[w], 0x10u << (lane * 8u));
    uint32_t rank = (old >> (lane * 8u + 4u)) & 0xFu;
    uint32_t below = 0;
    #pragma unroll
    for (uint32_t b = 0; b < 3; b++)
        if (b < lane) below += (old >> (b * 8u)) & 0xFu;
    uint32_t dest = base[w] + below + rank;
    z[dest] = ((unsigned long long)(uint32_t)i << 32) | (unsigned long long)__float_as_uint(v);
}

// One thread per word: 4 contiguous key-groups. Sort each tiny group by
// origidx (canonical concat order => bit-exact sums), emit heads.
__global__ void __launch_bounds__(256) headsum2_kernel(
        const uint32_t* __restrict__ cnt, const uint32_t* __restrict__ base,
        const unsigned long long* __restrict__ z,
        uint32_t* __restrict__ hcur,
        uint32_t* __restrict__ hord, uint32_t* __restrict__ hkey,
        uint32_t* __restrict__ hist) {
    int w = blockIdx.x * 256 + threadIdx.x;
    uint32_t nheads = 0;
    uint32_t lord[4], lkey[4];
    if (w < W4) {
        uint32_t c = cnt[w];
        uint32_t b = base[w];
        #pragma unroll
        for (uint32_t lane = 0; lane < 4; lane++) {
            uint32_t n = (c >> (lane * 8u)) & 0xFu;
            if (n == 0) continue;
            unsigned long long buf[15];
            for (uint32_t q = 0; q < n; q++) buf[q] = z[b + q];
            for (uint32_t a = 1; a < n; a++) {
                unsigned long long x = buf[a];
                int t = (int)a;
                while (t > 0 && buf[t - 1] > x) { buf[t] = buf[t - 1]; t--; }
                buf[t] = x;
            }
            float sum = 0.0f;
            for (uint32_t q = 0; q < n; q++)
                sum += __uint_as_float((uint32_t)buf[q]);
            lord[nheads] = ~f32_to_ord(__float_as_uint(sum));
            lkey[nheads] = ((uint32_t)w << 2) | lane;
            nheads++;
            b += n;
        }
    }
    typedef cub::BlockScan<uint32_t, 256> BS;
    __shared__ typename BS::TempStorage ts;
    __shared__ uint32_t s_base;
    uint32_t rank, total;
    BS(ts).ExclusiveSum(nheads, rank, total);
    if (threadIdx.x == 0) s_base = (total > 0) ? atomicAdd(hcur, total) : 0u;
    __syncthreads();
    uint32_t p = s_base + rank;
    for (uint32_t h = 0; h < nheads; h++) {
        hord[p + h] = lord[h];
        hkey[p + h] = lkey[h];
        atomicAdd(&hist[lord[h] >> 13], 1u);
    }
}

__global__ void coarse_kernel(const uint32_t* __restrict__ hist,
                              uint32_t* __restrict__ super) {
    typedef cub::BlockReduce<uint32_t, 256> BR;
    __shared__ typename BR::TempStorage ts;
    uint32_t v = hist[blockIdx.x * 256 + threadIdx.x];
    uint32_t s = BR(ts).Sum(v);
    if (threadIdx.x == 0) super[blockIdx.x] = s;
}

// Single block: threshold B + exclusive superbin scan.
__global__ void select_kernel(const uint32_t* __restrict__ super,
                              const uint32_t* __restrict__ hist,
                              uint32_t R, uint32_t* __restrict__ Bout,
                              uint32_t* __restrict__ superbase) {
    typedef cub::BlockScan<uint32_t, 1024> BS;
    __shared__ typename BS::TempStorage ts;
    __shared__ uint32_t s_sb, s_base2;
    if (threadIdx.x == 0) { s_sb = 0xFFFFFFFFu; s_base2 = 0; }
    __syncthreads();
    uint32_t v = super[threadIdx.x];
    uint32_t inc;
    BS(ts).InclusiveSum(v, inc);
    superbase[threadIdx.x] = inc - v;
    if (inc >= R && (inc - v) < R) { s_sb = threadIdx.x; s_base2 = inc - v; }
    __syncthreads();
    if (s_sb == 0xFFFFFFFFu) {
        if (threadIdx.x == 0) Bout[0] = 0xFFFFFFFFu;
        return;
    }
    uint32_t sb = s_sb, base = s_base2;
    __syncthreads();
    uint32_t h = (threadIdx.x < 256) ? hist[sb * 256 + threadIdx.x] : 0u;
    uint32_t inc1;
    BS(ts).InclusiveSum(h, inc1);
    if (threadIdx.x < 256) {
        uint32_t excl = inc1 - h;
        if (base + inc1 >= R && base + excl < R)
            Bout[0] = ((sb * 256u + threadIdx.x) + 1u) << 13;
    }
}

// Per-bin exclusive offsets + worklist of active bins (below threshold).
__global__ void __launch_bounds__(256) binbase_kernel(
        const uint32_t* __restrict__ hist, const uint32_t* __restrict__ superbase,
        const uint32_t* __restrict__ Bp, uint32_t R,
        uint32_t* __restrict__ binbase,
        uint32_t* __restrict__ wl, uint32_t* __restrict__ wcur) {
    int c = blockIdx.x, t = threadIdx.x;
    int bin = c * 256 + t;
    uint32_t v = hist[bin];
    typedef cub::BlockScan<uint32_t, 256> BS;
    __shared__ typename BS::TempStorage ts;
    __shared__ uint32_t s_wbase;
    uint32_t excl;
    BS(ts).ExclusiveSum(v, excl);
    uint32_t bb = superbase[c] + excl;
    binbase[bin] = bb;
    uint32_t Bbin = (*Bp) >> 13;
    uint32_t valid = (v > 0 && (uint32_t)bin < Bbin && bb < R) ? 1u : 0u;
    __syncthreads();
    uint32_t rank, total;
    BS(ts).ExclusiveSum(valid, rank, total);
    if (t == 0) s_wbase = (total > 0) ? atomicAdd(wcur, total) : 0u;
    __syncthreads();
    if (valid) wl[s_wbase + rank] = (uint32_t)bin;
}

// Candidates go straight to their bin region as u64 zips.
__global__ void __launch_bounds__(512) filter2_kernel(
        const uint32_t* __restrict__ hord, const uint32_t* __restrict__ hkey,
        const uint32_t* __restrict__ hcurp, const uint32_t* __restrict__ Bp,
        const uint32_t* __restrict__ binbase, uint32_t* __restrict__ bincur,
        unsigned long long* __restrict__ zbin) {
    int j = blockIdx.x * 512 + threadIdx.x;
    uint32_t H = *hcurp;
    if (j >= (int)H) return;
    uint32_t Bbin = (*Bp) >> 13;
    uint32_t x = hord[j];
    uint32_t bin = x >> 13;
    if (bin < Bbin) {
        uint32_t pos = binbase[bin] + atomicAdd(&bincur[bin], 1u);
        if (pos < (uint32_t)M2)
            zbin[pos] = ((unsigned long long)x << 24) | (unsigned long long)hkey[j];
    }
}

// Persistent blocks walk the worklist; sort each bin's zips ascending
// (= value desc, key asc, exact) and write output rows directly.
__global__ void __launch_bounds__(256) binsort_kernel(
        const uint32_t* __restrict__ wl, const uint32_t* __restrict__ wcurp,
        const uint32_t* __restrict__ hist, const uint32_t* __restrict__ binbase,
        const unsigned long long* __restrict__ zbin,
        uint32_t R, int write_idx, int write_val, int val_off,
        float* __restrict__ out) {
    __shared__ unsigned long long sz[CAPB];
    int t = threadIdx.x;
    uint32_t W = *wcurp;
    for (uint32_t wi = blockIdx.x; wi < W; wi += gridDim.x) {
        uint32_t b = wl[wi];
        uint32_t start = binbase[b];
        if (start >= (uint32_t)M2) continue;
        uint32_t n = hist[b];
        if (n > (uint32_t)M2 - start) n = (uint32_t)M2 - start;
        if (n == 0) continue;

        if (n <= (uint32_t)CAPB) {
            uint32_t m = 1;
            while (m < n) m <<= 1;
            for (uint32_t i = t; i < m; i += 256)
                sz[i] = (i < n) ? zbin[start + i] : ~0ull;
            __syncthreads();
            for (uint32_t k = 2; k <= m; k <<= 1) {
                for (uint32_t jj = k >> 1; jj > 0; jj >>= 1) {
                    for (uint32_t i = t; i < m; i += 256) {
                        uint32_t ixj = i ^ jj;
                        if (ixj > i) {
                            unsigned long long a = sz[i], c2 = sz[ixj];
                            bool up = ((i & k) == 0);
                            if ((a > c2) == up) { sz[i] = c2; sz[ixj] = a; }
                        }
                    }
                    __syncthreads();
                }
            }
            for (uint32_t r = t; r < n; r += 256) {
                uint32_t p = start + r;
                if (p < R) {
                    unsigned long long zp = sz[r];
                    uint32_t key = (uint32_t)(zp & 0xFFFFFFull);
                    if (write_idx) {
                        out[2 * p]     = (float)(key >> 12);
                        out[2 * p + 1] = (float)(key & 4095u);
                    }
                    if (write_val) {
                        uint32_t u = ~(uint32_t)(zp >> 24);
                        uint32_t bb = (u & 0x80000000u) ? (u ^ 0x80000000u) : ~u;
                        out[val_off + p] = __uint_as_float(bb);
                    }
                }
            }
            __syncthreads();
        } else {
            // fallback (never expected): tiled rank placement, O(n^2/256)
            for (uint32_t eb = 0; eb < n; eb += 256) {
                uint32_t e = eb + t;
                unsigned long long my = (e < n) ? zbin[start + e] : ~0ull;
                uint32_t rank = 0;
                for (uint32_t tb = 0; tb < n; tb += CAPB) {
                    uint32_t tn = n - tb; if (tn > (uint32_t)CAPB) tn = CAPB;
                    for (uint32_t i = t; i < tn; i += 256) sz[i] = zbin[start + tb + i];
                    __syncthreads();
                    if (e < n)
                        for (uint32_t i = 0; i < tn; i++) rank += (sz[i] < my) ? 1u : 0u;
                    __syncthreads();
                }
                if (e < n) {
                    uint32_t p = start + rank;
                    if (p < R) {
                        uint32_t key = (uint32_t)(my & 0xFFFFFFull);
                        if (write_idx) {
                            out[2 * p]     = (float)(key >> 12);
                            out[2 * p + 1] = (float)(key & 4095u);
                        }
                        if (write_val) {
                            uint32_t u = ~(uint32_t)(my >> 24);
                            uint32_t bb = (u & 0x80000000u) ? (u ^ 0x80000000u) : ~u;
                            out[val_off + p] = __uint_as_float(bb);
                        }
                    }
                }
            }
        }
    }
}

extern "C" void kernel_launch(void* const* d_in, const int* in_sizes, int n_in,
                              void* d_out, int out_size) {
    (void)n_in;
    const int*   samp = (const int*)d_in[0];
    const int*   ridx = (const int*)d_in[1];
    const float* rval = (const float*)d_in[2];
    const float* grad = (const float*)d_in[3];

    int S = in_sizes[0];
    int R = in_sizes[2];
    int K = S + R;
    if (K > MAX_K) K = MAX_K;

    double frac = (double)S / NUMEL_D;
    float adj = (float)(1.0 - frac * (1.0 - 0.95));

    uint32_t *cnt, *sums, *base, *hord, *hkey, *hist, *binbase, *bincur, *wl;
    uint32_t *super, *superbase, *Bp;
    unsigned long long* z;
    unsigned char* arena;
    cudaGetSymbolAddress((void**)&cnt,  g_cnt);
    cudaGetSymbolAddress((void**)&sums, g_sums);
    cudaGetSymbolAddress((void**)&base, g_base);
    cudaGetSymbolAddress((void**)&z,    g_z);
    cudaGetSymbolAddress((void**)&hord, g_hord);
    cudaGetSymbolAddress((void**)&hkey, g_hkey);
    cudaGetSymbolAddress((void**)&hist, g_hist);
    cudaGetSymbolAddress((void**)&binbase, g_binbase);
    cudaGetSymbolAddress((void**)&bincur,  g_bincur);
    cudaGetSymbolAddress((void**)&wl,      g_wl);
    cudaGetSymbolAddress((void**)&super,   g_super);
    cudaGetSymbolAddress((void**)&superbase, g_superbase);
    cudaGetSymbolAddress((void**)&Bp, g_B);
    cudaGetSymbolAddress((void**)&arena, g_temp);

    unsigned long long* zbin = (unsigned long long*)arena;          // 16MB region
    void* tmp = (void*)(arena + (16u << 20));                       // cub temp
    const size_t TMPB = (size_t)16u << 20;

    uint32_t* hcur = hist + HIST_BINS;
    uint32_t* wcur = hist + HIST_BINS + 1;

    const int GK512 = (K + 511) / 512;
    const int GW512 = (W4 + 511) / 512;

    // per-replay re-init (~19MB)
    cudaMemsetAsync(cnt,    0, (size_t)W4 * sizeof(uint32_t));           // 16MB
    cudaMemsetAsync(hist,   0, (HIST_BINS + 4) * sizeof(uint32_t));      // 1MB (covers hcur/wcur)
    cudaMemsetAsync(bincur, 0, HIST_BINS * sizeof(uint32_t));            // 1MB

    // 1) per-key multiplicity
    count_kernel<<<GK512, 512>>>(samp, ridx, S, K, cnt);

    // 2) per-word totals + exclusive scan -> group base offsets
    sums_kernel<<<GW512, 512>>>(cnt, sums);
    {
        size_t need = 0;
        cub::DeviceScan::ExclusiveSum(nullptr, need, sums, base, W4);
        if (need <= TMPB)
            cub::DeviceScan::ExclusiveSum(tmp, need, sums, base, W4);
    }

    // 3) scatter (origidx, valbits) into key-grouped storage
    scatter_kernel<<<GK512, 512>>>(samp, ridx, grad, rval, S, K, adj, cnt, base, z);

    // 4) per-word group sums (canonical order) -> dense heads + histogram
    headsum2_kernel<<<(W4 + 255) / 256, 256>>>(cnt, base, z, hcur, hord, hkey, hist);

    // 5) threshold B + superbin scan
    coarse_kernel<<<1024, 256>>>(hist, super);
    select_kernel<<<1, 1024>>>(super, hist, (uint32_t)R, Bp, superbase);

    // 6) per-bin offsets + worklist
    binbase_kernel<<<1024, 256>>>(hist, superbase, Bp, (uint32_t)R, binbase, wl, wcur);

    // 7) candidates -> bin regions (zips)
    filter2_kernel<<<(MAX_K + 511) / 512, 512>>>(hord, hkey, hcur, Bp,
                                                 binbase, bincur, zbin);

    // 8) per-bin sort + direct output write
    int write_idx = 1, write_val = 1, val_off = 2 * R;
    if (out_size == R)          { write_idx = 0; val_off = 0; }
    else if (out_size == 2 * R) { write_val = 0; }
    binsort_kernel<<<2048, 256>>>(wl, wcur, hist, binbase, zbin,
                                  (uint32_t)R, write_idx, write_val, val_off,
                                  (float*)d_out);
}

// round 15
// speedup vs baseline: 1.3141x; 1.3141x over previous
#include <cuda_runtime.h>
#include <cstdint>
#include <cub/cub.cuh>

// Problem constants
#define C_DIM     4096
#define NUMEL     16777216
#define W4        (NUMEL / 4)           // 4,194,304 count words
#define NUMEL_D   16777216.0
#define MAX_K     4500000               // >= S + R = 4,404,019
#define M2        1114112               // candidate sort size: R + 64K slack
#define HIST_BINS (1u << 18)            // ordkey >> 13
#define TEMP_BYTES (32u * 1024u * 1024u)

// Static device scratch (allocation-free per harness rules)
__device__ uint32_t g_cnt[W4];                 // count nibble + cursor nibble per key, 16MB
__device__ uint32_t g_base[W4];                // per-word group base (atomic-allocated)
__device__ unsigned long long g_z[MAX_K];      // key-grouped (origidx<<32)|valbits
__device__ uint32_t g_hord[MAX_K];             // dense head ordkeys
__device__ uint32_t g_hkey[MAX_K];             // dense head keys
__device__ uint32_t g_cord[M2], g_ckey[M2];    // candidates
__device__ uint32_t g_sord[M2], g_skey[M2];    // sorted candidates
__device__ uint32_t g_hist[HIST_BINS + 4];     // hist + [HIST_BINS]=hcur [+1]=ccur [+2]=gcur
__device__ uint32_t g_super[1024];
__device__ uint32_t g_B[1];
__device__ unsigned char g_temp[TEMP_BYTES];

static __device__ __forceinline__ uint32_t f32_to_ord(uint32_t b) {
    return b ^ ((uint32_t)((int32_t)b >> 31) | 0x80000000u);
}
static __device__ __forceinline__ uint32_t make_key(const int* __restrict__ samp,
                                                    const int* __restrict__ ridx,
                                                    int S, int i) {
    if (i < S) return (uint32_t)samp[i];
    int r = i - S;
    return (uint32_t)ridx[2 * r] * (uint32_t)C_DIM + (uint32_t)ridx[2 * r + 1];
}

__global__ void __launch_bounds__(512) count_kernel(
        const int* __restrict__ samp, const int* __restrict__ ridx,
        int S, int K, uint32_t* __restrict__ cnt) {
    int i = blockIdx.x * 512 + threadIdx.x;
    if (i >= K) return;
    uint32_t key = make_key(samp, ridx, S, i);
    atomicAdd(&cnt[key >> 2], 1u << ((key & 3u) * 8u));
}

// Group-base allocation WITHOUT a global scan: order of groups is arbitrary
// (canonicalized later by sort2+outfix); only contiguity matters.
__global__ void __launch_bounds__(512) basealloc_kernel(
        const uint32_t* __restrict__ cnt, uint32_t* __restrict__ base,
        uint32_t* __restrict__ gcur) {
    int w = blockIdx.x * 512 + threadIdx.x;
    uint32_t tot = 0;
    if (w < W4) {
        uint32_t c = cnt[w];
        uint32_t p = (c & 0x00FF00FFu) + ((c >> 8) & 0x00FF00FFu);
        tot = (p & 0xFFFFu) + (p >> 16);
    }
    typedef cub::BlockScan<uint32_t, 512> BS;
    __shared__ typename BS::TempStorage ts;
    __shared__ uint32_t s_base;
    uint32_t rank, total;
    BS(ts).ExclusiveSum(tot, rank, total);
    if (threadIdx.x == 0) s_base = (total > 0) ? atomicAdd(gcur, total) : 0u;
    __syncthreads();
    if (w < W4) base[w] = s_base + rank;
}

// dest = base[word] + lanes-below counts + intra-key rank (cursor high nibble).
__global__ void __launch_bounds__(512) scatter_kernel(
        const int* __restrict__ samp, const int* __restrict__ ridx,
        const float* __restrict__ grad, const float* __restrict__ rval,
        int S, int K, float adj,
        uint32_t* __restrict__ cnt, const uint32_t* __restrict__ base,
        unsigned long long* __restrict__ z) {
    int i = blockIdx.x * 512 + threadIdx.x;
    if (i >= K) return;
    uint32_t key = make_key(samp, ridx, S, i);
    float v = (i < S) ? fabsf(grad[i]) : adj * rval[i - S];
    uint32_t w = key >> 2, lane = key & 3u;
    uint32_t old = atomicAdd(&cnt[w], 0x10u << (lane * 8u));
    uint32_t rank = (old >> (lane * 8u + 4u)) & 0xFu;
    uint32_t below = 0;
    #pragma unroll
    for (uint32_t b = 0; b < 3; b++)
        if (b < lane) below += (old >> (b * 8u)) & 0xFu;
    uint32_t dest = base[w] + below + rank;
    z[dest] = ((unsigned long long)(uint32_t)i << 32) | (unsigned long long)__float_as_uint(v);
}

// One thread per word: 4 contiguous key-groups. Sort each tiny group by
// origidx (canonical concat order => bit-exact sums), emit heads densely.
__global__ void __launch_bounds__(256) headsum2_kernel(
        const uint32_t* __restrict__ cnt, const uint32_t* __restrict__ base,
        const unsigned long long* __restrict__ z,
        uint32_t* __restrict__ hcur,
        uint32_t* __restrict__ hord, uint32_t* __restrict__ hkey,
        uint32_t* __restrict__ hist) {
    int w = blockIdx.x * 256 + threadIdx.x;
    uint32_t nheads = 0;
    uint32_t lord[4], lkey[4];
    if (w < W4) {
        uint32_t c = cnt[w];
        uint32_t b = base[w];
        #pragma unroll
        for (uint32_t lane = 0; lane < 4; lane++) {
            uint32_t n = (c >> (lane * 8u)) & 0xFu;
            if (n == 0) continue;
            unsigned long long buf[15];
            for (uint32_t q = 0; q < n; q++) buf[q] = z[b + q];
            for (uint32_t a = 1; a < n; a++) {
                unsigned long long x = buf[a];
                int t = (int)a;
                while (t > 0 && buf[t - 1] > x) { buf[t] = buf[t - 1]; t--; }
                buf[t] = x;
            }
            float sum = 0.0f;
            for (uint32_t q = 0; q < n; q++)
                sum += __uint_as_float((uint32_t)buf[q]);
            lord[nheads] = ~f32_to_ord(__float_as_uint(sum));
            lkey[nheads] = ((uint32_t)w << 2) | lane;
            nheads++;
            b += n;
        }
    }
    typedef cub::BlockScan<uint32_t, 256> BS;
    __shared__ typename BS::TempStorage ts;
    __shared__ uint32_t s_base;
    uint32_t rank, total;
    BS(ts).ExclusiveSum(nheads, rank, total);
    if (threadIdx.x == 0) s_base = (total > 0) ? atomicAdd(hcur, total) : 0u;
    __syncthreads();
    uint32_t p = s_base + rank;
    for (uint32_t h = 0; h < nheads; h++) {
        hord[p + h] = lord[h];
        hkey[p + h] = lkey[h];
        atomicAdd(&hist[lord[h] >> 13], 1u);
    }
}

__global__ void coarse_kernel(const uint32_t* __restrict__ hist,
                              uint32_t* __restrict__ super) {
    typedef cub::BlockReduce<uint32_t, 256> BR;
    __shared__ typename BR::TempStorage ts;
    uint32_t v = hist[blockIdx.x * 256 + threadIdx.x];
    uint32_t s = BR(ts).Sum(v);
    if (threadIdx.x == 0) super[blockIdx.x] = s;
}

// Single block: smallest bin boundary B with #heads{ordkey < B} >= R.
__global__ void select_kernel(const uint32_t* __restrict__ super,
                              const uint32_t* __restrict__ hist,
                              uint32_t R, uint32_t* __restrict__ Bout) {
    typedef cub::BlockScan<uint32_t, 1024> BS;
    __shared__ typename BS::TempStorage ts;
    __shared__ uint32_t s_sb, s_base2;
    if (threadIdx.x == 0) { s_sb = 0xFFFFFFFFu; s_base2 = 0; }
    __syncthreads();
    uint32_t v = super[threadIdx.x];
    uint32_t inc;
    BS(ts).InclusiveSum(v, inc);
    if (inc >= R && (inc - v) < R) { s_sb = threadIdx.x; s_base2 = inc - v; }
    __syncthreads();
    if (s_sb == 0xFFFFFFFFu) {
        if (threadIdx.x == 0) Bout[0] = 0xFFFFFFFFu;
        return;
    }
    uint32_t sb = s_sb, base = s_base2;
    __syncthreads();
    uint32_t h = (threadIdx.x < 256) ? hist[sb * 256 + threadIdx.x] : 0u;
    uint32_t inc1;
    BS(ts).InclusiveSum(h, inc1);
    if (threadIdx.x < 256) {
        uint32_t excl = inc1 - h;
        if (base + inc1 >= R && base + excl < R)
            Bout[0] = ((sb * 256u + threadIdx.x) + 1u) << 13;
    }
}

// Block-aggregated candidate append over the dense head list.
__global__ void __launch_bounds__(512) filter_kernel(
        const uint32_t* __restrict__ hord, const uint32_t* __restrict__ hkey,
        const uint32_t* __restrict__ hcurp, const uint32_t* __restrict__ Bp,
        uint32_t* __restrict__ ccur,
        uint32_t* __restrict__ cord, uint32_t* __restrict__ ckey) {
    int j = blockIdx.x * 512 + threadIdx.x;
    uint32_t H = *hcurp;
    uint32_t B = *Bp;
    uint32_t x = (j < (int)H) ? hord[j] : 0xFFFFFFFFu;
    uint32_t pred = (x < B) ? 1u : 0u;
    typedef cub::BlockScan<uint32_t, 512> BS;
    __shared__ typename BS::TempStorage ts;
    __shared__ uint32_t s_base;
    uint32_t rank, total;
    BS(ts).ExclusiveSum(pred, rank, total);
    if (threadIdx.x == 0) s_base = (total > 0) ? atomicAdd(ccur, total) : 0u;
    __syncthreads();
    if (pred) {
        uint32_t p = s_base + rank;
        if (p < (uint32_t)M2) {
            cord[p] = x;
            ckey[p] = hkey[j];
        }
    }
}

// Merged tie-fix + output: each run-start thread sorts its equal-value run's
// keys ascending (exact lax.top_k tie-break) and writes those output rows.
__global__ void outfix_kernel(const uint32_t* __restrict__ sord,
                              uint32_t* __restrict__ skey,
                              uint32_t R, int write_idx, int write_val, int val_off,
                              float* __restrict__ out) {
    int j = blockIdx.x * blockDim.x + threadIdx.x;
    if (j >= M2) return;
    uint32_t o = sord[j];
    if (o == 0xFFFFFFFFu) return;                    // pad
    if (j > 0 && sord[j - 1] == o) return;           // not run start
    if ((uint32_t)j >= R) return;                    // run entirely beyond output
    int e = j + 1;
    while (e < M2 && sord[e] == o) e++;
    // sort run keys ascending (tiny runs)
    for (int a = j + 1; a < e; a++) {
        uint32_t kx = skey[a];
        int t = a;
        while (t > j && skey[t - 1] > kx) { skey[t] = skey[t - 1]; t--; }
        skey[t] = kx;
    }
    uint32_t u = ~o;
    uint32_t vb = (u & 0x80000000u) ? (u ^ 0x80000000u) : ~u;
    float vf = __uint_as_float(vb);
    for (int p = j; p < e && (uint32_t)p < R; p++) {
        uint32_t key = skey[p];
        if (write_idx) {
            out[2 * p]     = (float)(key >> 12);
            out[2 * p + 1] = (float)(key & 4095u);
        }
        if (write_val) out[val_off + p] = vf;
    }
}

extern "C" void kernel_launch(void* const* d_in, const int* in_sizes, int n_in,
                              void* d_out, int out_size) {
    (void)n_in;
    const int*   samp = (const int*)d_in[0];
    const int*   ridx = (const int*)d_in[1];
    const float* rval = (const float*)d_in[2];
    const float* grad = (const float*)d_in[3];

    int S = in_sizes[0];
    int R = in_sizes[2];
    int K = S + R;
    if (K > MAX_K) K = MAX_K;

    double frac = (double)S / NUMEL_D;
    float adj = (float)(1.0 - frac * (1.0 - 0.95));

    uint32_t *cnt, *base, *hord, *hkey, *cord, *ckey, *sord, *skey;
    uint32_t *hist, *super, *Bp;
    unsigned long long* z;
    void* tmp;
    cudaGetSymbolAddress((void**)&cnt,  g_cnt);
    cudaGetSymbolAddress((void**)&base, g_base);
    cudaGetSymbolAddress((void**)&z,    g_z);
    cudaGetSymbolAddress((void**)&hord, g_hord);
    cudaGetSymbolAddress((void**)&hkey, g_hkey);
    cudaGetSymbolAddress((void**)&cord, g_cord);
    cudaGetSymbolAddress((void**)&ckey, g_ckey);
    cudaGetSymbolAddress((void**)&sord, g_sord);
    cudaGetSymbolAddress((void**)&skey, g_skey);
    cudaGetSymbolAddress((void**)&hist, g_hist);
    cudaGetSymbolAddress((void**)&super,g_super);
    cudaGetSymbolAddress((void**)&Bp,   g_B);
    cudaGetSymbolAddress(&tmp, g_temp);
    const size_t TMPB = (size_t)TEMP_BYTES;

    uint32_t* hcur = hist + HIST_BINS;
    uint32_t* ccur = hist + HIST_BINS + 1;
    uint32_t* gcur = hist + HIST_BINS + 2;

    const int GK512 = (K + 511) / 512;
    const int GW512 = (W4 + 511) / 512;

    // per-replay re-init (one 16MB + one 1MB + one 4.3MB)
    cudaMemsetAsync(cnt,  0,    (size_t)W4 * sizeof(uint32_t));
    cudaMemsetAsync(hist, 0,    (HIST_BINS + 4) * sizeof(uint32_t));  // covers hcur/ccur/gcur
    cudaMemsetAsync(cord, 0xFF, (size_t)M2 * sizeof(uint32_t));       // pads sort last

    // 1) per-key multiplicity
    count_kernel<<<GK512, 512>>>(samp, ridx, S, K, cnt);

    // 2) group bases via atomic allocation (no scan; order canonicalized later)
    basealloc_kernel<<<GW512, 512>>>(cnt, base, gcur);

    // 3) scatter (origidx, valbits) into contiguous key groups
    scatter_kernel<<<GK512, 512>>>(samp, ridx, grad, rval, S, K, adj, cnt, base, z);

    // 4) per-word group sums (canonical origidx order) -> dense heads + histogram
    headsum2_kernel<<<(W4 + 255) / 256, 256>>>(cnt, base, z, hcur, hord, hkey, hist);

    // 5) threshold B (bin-granular, keeps all ties of the R-th element)
    coarse_kernel<<<1024, 256>>>(hist, super);
    select_kernel<<<1, 1024>>>(super, hist, (uint32_t)R, Bp);

    // 6) candidate filter over dense heads
    filter_kernel<<<(MAX_K + 511) / 512, 512>>>(hord, hkey, hcur, Bp, ccur, cord, ckey);

    // 7) sort candidates by ordkey (stable, deterministic on values)
    {
        size_t need = 0;
        cub::DeviceRadixSort::SortPairs(nullptr, need, cord, sord, ckey, skey, M2, 0, 32);
        if (need <= TMPB)
            cub::DeviceRadixSort::SortPairs(tmp, need, cord, sord, ckey, skey, M2, 0, 32);
    }

    // 8) merged tie-fix + output write
    int write_idx = 1, write_val = 1, val_off = 2 * R;
    if (out_size == R)          { write_idx = 0; val_off = 0; }
    else if (out_size == 2 * R) { write_val = 0; }
    outfix_kernel<<<(M2 + 255) / 256, 256>>>(sord, skey, (uint32_t)R,
                                             write_idx, write_val, val_off,
                                             (float*)d_out);
}

// round 16
// speedup vs baseline: 1.3821x; 1.0518x over previous
#include <cuda_runtime.h>
#include <cstdint>
#include <cub/cub.cuh>

// Problem constants
#define C_DIM     4096
#define NUMEL     16777216
#define W4        (NUMEL / 4)           // 4,194,304 count words
#define NUMEL_D   16777216.0
#define MAX_K     4500000               // >= S + R = 4,404,019
#define M2        1114112               // candidate sort size: R + 64K slack
#define HIST_BINS (1u << 18)            // ordkey >> 13
#define TEMP_BYTES (32u * 1024u * 1024u)

// Static device scratch (allocation-free per harness rules)
__device__ uint32_t g_cnt[W4];                 // count nibble + cursor nibble per key, 16MB
__device__ uint32_t g_base[W4];                // per-word group base (atomic-allocated)
__device__ unsigned long long g_z[MAX_K];      // key-grouped (origidx<<32)|valbits
__device__ uint32_t g_hord[MAX_K];             // dense head ordkeys
__device__ uint32_t g_hkey[MAX_K];             // dense head keys
__device__ uint32_t g_cord[M2], g_ckey[M2];    // candidates
__device__ uint32_t g_sord[M2], g_skey[M2];    // sorted candidates
__device__ uint32_t g_hist[HIST_BINS + 4];     // hist + [HIST_BINS]=hcur [+1]=ccur [+2]=gcur
__device__ uint32_t g_super[1024];
__device__ uint32_t g_B[1];
__device__ unsigned char g_temp[TEMP_BYTES];

static __device__ __forceinline__ uint32_t f32_to_ord(uint32_t b) {
    return b ^ ((uint32_t)((int32_t)b >> 31) | 0x80000000u);
}
static __device__ __forceinline__ uint32_t make_key(const int* __restrict__ samp,
                                                    const int* __restrict__ ridx,
                                                    int S, int i) {
    if (i < S) return (uint32_t)samp[i];
    int r = i - S;
    return (uint32_t)ridx[2 * r] * (uint32_t)C_DIM + (uint32_t)ridx[2 * r + 1];
}

__global__ void __launch_bounds__(512) count_kernel(
        const int* __restrict__ samp, const int* __restrict__ ridx,
        int S, int K, uint32_t* __restrict__ cnt) {
    int i = blockIdx.x * 512 + threadIdx.x;
    if (i >= K) return;
    uint32_t key = make_key(samp, ridx, S, i);
    atomicAdd(&cnt[key >> 2], 1u << ((key & 3u) * 8u));
}

// Group-base allocation WITHOUT a global scan: group order is arbitrary
// (canonicalized later by sort2+outfix); only contiguity matters.
__global__ void __launch_bounds__(512) basealloc_kernel(
        const uint32_t* __restrict__ cnt, uint32_t* __restrict__ base,
        uint32_t* __restrict__ gcur) {
    int w = blockIdx.x * 512 + threadIdx.x;
    uint32_t tot = 0;
    if (w < W4) {
        uint32_t c = cnt[w];
        uint32_t p = (c & 0x00FF00FFu) + ((c >> 8) & 0x00FF00FFu);
        tot = (p & 0xFFFFu) + (p >> 16);
    }
    typedef cub::BlockScan<uint32_t, 512> BS;
    __shared__ typename BS::TempStorage ts;
    __shared__ uint32_t s_base;
    uint32_t rank, total;
    BS(ts).ExclusiveSum(tot, rank, total);
    if (threadIdx.x == 0) s_base = (total > 0) ? atomicAdd(gcur, total) : 0u;
    __syncthreads();
    if (w < W4) base[w] = s_base + rank;
}

// dest = base[word] + lanes-below counts + intra-key rank (cursor high nibble).
__global__ void __launch_bounds__(512) scatter_kernel(
        const int* __restrict__ samp, const int* __restrict__ ridx,
        const float* __restrict__ grad, const float* __restrict__ rval,
        int S, int K, float adj,
        uint32_t* __restrict__ cnt, const uint32_t* __restrict__ base,
        unsigned long long* __restrict__ z) {
    int i = blockIdx.x * 512 + threadIdx.x;
    if (i >= K) return;
    uint32_t key = make_key(samp, ridx, S, i);
    float v = (i < S) ? fabsf(grad[i]) : adj * rval[i - S];
    uint32_t w = key >> 2, lane = key & 3u;
    uint32_t old = atomicAdd(&cnt[w], 0x10u << (lane * 8u));
    uint32_t rank = (old >> (lane * 8u + 4u)) & 0xFu;
    uint32_t below = 0;
    #pragma unroll
    for (uint32_t b = 0; b < 3; b++)
        if (b < lane) below += (old >> (b * 8u)) & 0xFu;
    uint32_t dest = base[w] + below + rank;
    z[dest] = ((unsigned long long)(uint32_t)i << 32) | (unsigned long long)__float_as_uint(v);
}

// One thread per word: 4 contiguous key-groups. Fast paths by multiplicity:
// n==1 direct; n==2 commutative add (bit-exact); n>=3 min-origidx selection
// straight from global (no local-memory buffers anywhere).
__global__ void __launch_bounds__(256) headsum2_kernel(
        const uint32_t* __restrict__ cnt, const uint32_t* __restrict__ base,
        const unsigned long long* __restrict__ z,
        uint32_t* __restrict__ hcur,
        uint32_t* __restrict__ hord, uint32_t* __restrict__ hkey,
        uint32_t* __restrict__ hist) {
    int w = blockIdx.x * 256 + threadIdx.x;
    uint32_t lord[4], lkey[4];
    bool lv[4] = {false, false, false, false};
    uint32_t nheads = 0;
    if (w < W4) {
        uint32_t c = cnt[w];
        uint32_t b = base[w];
        #pragma unroll
        for (uint32_t lane = 0; lane < 4; lane++) {
            uint32_t n = (c >> (lane * 8u)) & 0xFu;
            if (n != 0) {
                float sum;
                if (n == 1) {
                    sum = __uint_as_float((uint32_t)z[b]);
                } else if (n == 2) {
                    // float add commutative => order-free, bit-exact
                    sum = __uint_as_float((uint32_t)z[b]) +
                          __uint_as_float((uint32_t)z[b + 1]);
                } else {
                    // rare (>=3): sequential sum in original-index order via
                    // repeated min-selection from global (n <= ~9)
                    sum = 0.0f;
                    uint32_t lastEx = 0;
                    for (uint32_t s = 0; s < n; s++) {
                        uint32_t bestIdx = 0xFFFFFFFFu, bestVal = 0;
                        for (uint32_t q = 0; q < n; q++) {
                            unsigned long long e = z[b + q];
                            uint32_t oi = (uint32_t)(e >> 32);
                            if (oi >= lastEx && oi < bestIdx) {
                                bestIdx = oi;
                                bestVal = (uint32_t)e;
                            }
                        }
                        sum += __uint_as_float(bestVal);
                        lastEx = bestIdx + 1u;
                    }
                }
                lord[lane] = ~f32_to_ord(__float_as_uint(sum));
                lkey[lane] = ((uint32_t)w << 2) | lane;
                lv[lane] = true;
                nheads++;
                b += n;
            }
        }
    }
    typedef cub::BlockScan<uint32_t, 256> BS;
    __shared__ typename BS::TempStorage ts;
    __shared__ uint32_t s_base;
    uint32_t rank, total;
    BS(ts).ExclusiveSum(nheads, rank, total);
    if (threadIdx.x == 0) s_base = (total > 0) ? atomicAdd(hcur, total) : 0u;
    __syncthreads();
    uint32_t p = s_base + rank;
    #pragma unroll
    for (uint32_t lane = 0; lane < 4; lane++) {
        if (lv[lane]) {
            hord[p] = lord[lane];
            hkey[p] = lkey[lane];
            atomicAdd(&hist[lord[lane] >> 13], 1u);
            p++;
        }
    }
}

__global__ void coarse_kernel(const uint32_t* __restrict__ hist,
                              uint32_t* __restrict__ super) {
    typedef cub::BlockReduce<uint32_t, 256> BR;
    __shared__ typename BR::TempStorage ts;
    uint32_t v = hist[blockIdx.x * 256 + threadIdx.x];
    uint32_t s = BR(ts).Sum(v);
    if (threadIdx.x == 0) super[blockIdx.x] = s;
}

// Single block: smallest bin boundary B with #heads{ordkey < B} >= R.
__global__ void select_kernel(const uint32_t* __restrict__ super,
                              const uint32_t* __restrict__ hist,
                              uint32_t R, uint32_t* __restrict__ Bout) {
    typedef cub::BlockScan<uint32_t, 1024> BS;
    __shared__ typename BS::TempStorage ts;
    __shared__ uint32_t s_sb, s_base2;
    if (threadIdx.x == 0) { s_sb = 0xFFFFFFFFu; s_base2 = 0; }
    __syncthreads();
    uint32_t v = super[threadIdx.x];
    uint32_t inc;
    BS(ts).InclusiveSum(v, inc);
    if (inc >= R && (inc - v) < R) { s_sb = threadIdx.x; s_base2 = inc - v; }
    __syncthreads();
    if (s_sb == 0xFFFFFFFFu) {
        if (threadIdx.x == 0) Bout[0] = 0xFFFFFFFFu;
        return;
    }
    uint32_t sb = s_sb, base = s_base2;
    __syncthreads();
    uint32_t h = (threadIdx.x < 256) ? hist[sb * 256 + threadIdx.x] : 0u;
    uint32_t inc1;
    BS(ts).InclusiveSum(h, inc1);
    if (threadIdx.x < 256) {
        uint32_t excl = inc1 - h;
        if (base + inc1 >= R && base + excl < R)
            Bout[0] = ((sb * 256u + threadIdx.x) + 1u) << 13;
    }
}

// Block-aggregated candidate append over the dense head list.
__global__ void __launch_bounds__(512) filter_kernel(
        const uint32_t* __restrict__ hord, const uint32_t* __restrict__ hkey,
        const uint32_t* __restrict__ hcurp, const uint32_t* __restrict__ Bp,
        uint32_t* __restrict__ ccur,
        uint32_t* __restrict__ cord, uint32_t* __restrict__ ckey) {
    int j = blockIdx.x * 512 + threadIdx.x;
    uint32_t H = *hcurp;
    uint32_t B = *Bp;
    uint32_t x = (j < (int)H) ? hord[j] : 0xFFFFFFFFu;
    uint32_t pred = (x < B) ? 1u : 0u;
    typedef cub::BlockScan<uint32_t, 512> BS;
    __shared__ typename BS::TempStorage ts;
    __shared__ uint32_t s_base;
    uint32_t rank, total;
    BS(ts).ExclusiveSum(pred, rank, total);
    if (threadIdx.x == 0) s_base = (total > 0) ? atomicAdd(ccur, total) : 0u;
    __syncthreads();
    if (pred) {
        uint32_t p = s_base + rank;
        if (p < (uint32_t)M2) {
            cord[p] = x;
            ckey[p] = hkey[j];
        }
    }
}

// Merged tie-fix + output: each run-start thread sorts its equal-value run's
// keys ascending (exact lax.top_k tie-break) and writes those output rows.
__global__ void outfix_kernel(const uint32_t* __restrict__ sord,
                              uint32_t* __restrict__ skey,
                              uint32_t R, int write_idx, int write_val, int val_off,
                              float* __restrict__ out) {
    int j = blockIdx.x * blockDim.x + threadIdx.x;
    if (j >= M2) return;
    uint32_t o = sord[j];
    if (o == 0xFFFFFFFFu) return;                    // pad
    if (j > 0 && sord[j - 1] == o) return;           // not run start
    if ((uint32_t)j >= R) return;                    // run entirely beyond output
    int e = j + 1;
    while (e < M2 && sord[e] == o) e++;
    for (int a = j + 1; a < e; a++) {                // tiny runs: insertion sort
        uint32_t kx = skey[a];
        int t = a;
        while (t > j && skey[t - 1] > kx) { skey[t] = skey[t - 1]; t--; }
        skey[t] = kx;
    }
    uint32_t u = ~o;
    uint32_t vb = (u & 0x80000000u) ? (u ^ 0x80000000u) : ~u;
    float vf = __uint_as_float(vb);
    for (int p = j; p < e && (uint32_t)p < R; p++) {
        uint32_t key = skey[p];
        if (write_idx) {
            out[2 * p]     = (float)(key >> 12);
            out[2 * p + 1] = (float)(key & 4095u);
        }
        if (write_val) out[val_off + p] = vf;
    }
}

extern "C" void kernel_launch(void* const* d_in, const int* in_sizes, int n_in,
                              void* d_out, int out_size) {
    (void)n_in;
    const int*   samp = (const int*)d_in[0];
    const int*   ridx = (const int*)d_in[1];
    const float* rval = (const float*)d_in[2];
    const float* grad = (const float*)d_in[3];

    int S = in_sizes[0];
    int R = in_sizes[2];
    int K = S + R;
    if (K > MAX_K) K = MAX_K;

    double frac = (double)S / NUMEL_D;
    float adj = (float)(1.0 - frac * (1.0 - 0.95));

    uint32_t *cnt, *base, *hord, *hkey, *cord, *ckey, *sord, *skey;
    uint32_t *hist, *super, *Bp;
    unsigned long long* z;
    void* tmp;
    cudaGetSymbolAddress((void**)&cnt,  g_cnt);
    cudaGetSymbolAddress((void**)&base, g_base);
    cudaGetSymbolAddress((void**)&z,    g_z);
    cudaGetSymbolAddress((void**)&hord, g_hord);
    cudaGetSymbolAddress((void**)&hkey, g_hkey);
    cudaGetSymbolAddress((void**)&cord, g_cord);
    cudaGetSymbolAddress((void**)&ckey, g_ckey);
    cudaGetSymbolAddress((void**)&sord, g_sord);
    cudaGetSymbolAddress((void**)&skey, g_skey);
    cudaGetSymbolAddress((void**)&hist, g_hist);
    cudaGetSymbolAddress((void**)&super,g_super);
    cudaGetSymbolAddress((void**)&Bp,   g_B);
    cudaGetSymbolAddress(&tmp, g_temp);
    const size_t TMPB = (size_t)TEMP_BYTES;

    uint32_t* hcur = hist + HIST_BINS;
    uint32_t* ccur = hist + HIST_BINS + 1;
    uint32_t* gcur = hist + HIST_BINS + 2;

    const int GK512 = (K + 511) / 512;
    const int GW512 = (W4 + 511) / 512;

    // per-replay re-init
    cudaMemsetAsync(cnt,  0,    (size_t)W4 * sizeof(uint32_t));       // 16MB
    cudaMemsetAsync(hist, 0,    (HIST_BINS + 4) * sizeof(uint32_t));  // 1MB (covers counters)
    cudaMemsetAsync(cord, 0xFF, (size_t)M2 * sizeof(uint32_t));       // pads sort last

    // 1) per-key multiplicity
    count_kernel<<<GK512, 512>>>(samp, ridx, S, K, cnt);

    // 2) group bases via atomic allocation (no scan; order canonicalized later)
    basealloc_kernel<<<GW512, 512>>>(cnt, base, gcur);

    // 3) scatter (origidx, valbits) into contiguous key groups
    scatter_kernel<<<GK512, 512>>>(samp, ridx, grad, rval, S, K, adj, cnt, base, z);

    // 4) per-word group sums (fast paths; canonical order where it matters)
    headsum2_kernel<<<(W4 + 255) / 256, 256>>>(cnt, base, z, hcur, hord, hkey, hist);

    // 5) threshold B (bin-granular, keeps all ties of the R-th element)
    coarse_kernel<<<1024, 256>>>(hist, super);
    select_kernel<<<1, 1024>>>(super, hist, (uint32_t)R, Bp);

    // 6) candidate filter over dense heads
    filter_kernel<<<(MAX_K + 511) / 512, 512>>>(hord, hkey, hcur, Bp, ccur, cord, ckey);

    // 7) sort candidates by ordkey (stable, deterministic on values)
    {
        size_t need = 0;
        cub::DeviceRadixSort::SortPairs(nullptr, need, cord, sord, ckey, skey, M2, 0, 32);
        if (need <= TMPB)
            cub::DeviceRadixSort::SortPairs(tmp, need, cord, sord, ckey, skey, M2, 0, 32);
    }

    // 8) merged tie-fix + output write
    int write_idx = 1, write_val = 1, val_off = 2 * R;
    if (out_size == R)          { write_idx = 0; val_off = 0; }
    else if (out_size == 2 * R) { write_val = 0; }
    outfix_kernel<<<(M2 + 255) / 256, 256>>>(sord, skey, (uint32_t)R,
                                             write_idx, write_val, val_off,
                                             (float*)d_out);
}